// round 7
// baseline (speedup 1.0000x reference)
#include <cuda_runtime.h>
#include <cuda_bf16.h>
#include <cstdint>

#define NITER   50
#define EPSF    0.1f
#define PCOEF   (1.0f/1.1f)
#define LOGHUGE 69.07755279f   /* log(1e30) */
#define NB      256
#define NN      256
#define KPAD    264            /* padded row length (bf16): 528B stride -> ldmatrix conflict-free */
#define DXC     (1.0f/256.0f)
#define DYC     (1.0f/256.0f)
#define PI2F    1.57079632679489662f

typedef unsigned long long u64;

struct __align__(16) Smem {
    uint16_t K0[NN * KPAD];   // 135168 B, bf16 kernel matrix K0 = exp(-C/eps)
    float z[NN];              // f32 z (epilogue only)
    float w[NN];              // f32 w (epilogue only)
    float csave[NN];          // final col sums (epilogue only)
    uint16_t zbp[NN];         // packed bf16 z in B-frag (pidx) order
    uint16_t wbp[NN];         // plain bf16 w (col-pass A operand)
    float part[16][NN];       // col-pass partials
    float red[16];
};

__device__ __forceinline__ unsigned pack_bf16(float a, float b) {
    __nv_bfloat162 h = __floats2bfloat162_rn(a, b);
    return *reinterpret_cast<unsigned*>(&h);
}
__device__ __forceinline__ uint16_t to_bf16u(float a) {
    __nv_bfloat16 h = __float2bfloat16(a);
    return *reinterpret_cast<uint16_t*>(&h);
}
// packed B-frag index for column j: (chunk=j>>4, q=(j&7)>>1, h=(j>>3)&1, e=j&1)
__device__ __forceinline__ int pidx(int j) {
    return (j & ~15) | (((j & 7) >> 1) << 2) | (((j >> 3) & 1) << 1) | (j & 1);
}

__device__ __forceinline__ void ldmx4(uint32_t addr, uint32_t& r0, uint32_t& r1, uint32_t& r2, uint32_t& r3) {
    asm volatile("ldmatrix.sync.aligned.m8n8.x4.shared.b16 {%0,%1,%2,%3}, [%4];"
                 : "=r"(r0), "=r"(r1), "=r"(r2), "=r"(r3) : "r"(addr));
}
__device__ __forceinline__ uint32_t movm(uint32_t s) {
    uint32_t d;
    asm("movmatrix.sync.aligned.m8n8.trans.b16 %0, %1;" : "=r"(d) : "r"(s));
    return d;
}
__device__ __forceinline__ void mma_bf16(float& d0, float& d1, float& d2, float& d3,
                                         uint32_t a0, uint32_t a1, uint32_t a2, uint32_t a3,
                                         uint32_t b0, uint32_t b1) {
    asm volatile("mma.sync.aligned.m16n8k16.row.col.f32.bf16.bf16.f32 "
                 "{%0,%1,%2,%3},{%4,%5,%6,%7},{%8,%9},{%0,%1,%2,%3};"
                 : "+f"(d0), "+f"(d1), "+f"(d2), "+f"(d3)
                 : "r"(a0), "r"(a1), "r"(a2), "r"(a3), "r"(b0), "r"(b1));
}

__global__ void __launch_bounds__(512, 1)
wfr_kernel(const float* __restrict__ D, float* __restrict__ out)
{
    extern __shared__ char smraw[];
    Smem* sm = reinterpret_cast<Smem*>(smraw);
    const int b = blockIdx.x;
    const int t = threadIdx.x;
    const float* __restrict__ Db = D + (size_t)b * (NN * NN);

    // ---------------- Prologue: K0 = (cos(min(2D,pi/2)) + 1e-5)^20  (bf16, SMEM) ---------
    {
        const float4* __restrict__ D4 = reinterpret_cast<const float4*>(Db);
        #pragma unroll 4
        for (int k = 0; k < 32; k++) {
            int i4 = t + k * 512;
            float4 d = D4[i4];
            int e = i4 << 2;
            int i = e >> 8, j = e & (NN - 1);
            float c0 = __cosf(fminf(d.x * 2.0f, PI2F)) + 1e-5f;
            float c1 = __cosf(fminf(d.y * 2.0f, PI2F)) + 1e-5f;
            float c2 = __cosf(fminf(d.z * 2.0f, PI2F)) + 1e-5f;
            float c3 = __cosf(fminf(d.w * 2.0f, PI2F)) + 1e-5f;
            float k0 = exp2f(20.0f * __log2f(c0));
            float k1 = exp2f(20.0f * __log2f(c1));
            float k2 = exp2f(20.0f * __log2f(c2));
            float k3 = exp2f(20.0f * __log2f(c3));
            uint2 pk = make_uint2(pack_bf16(k0, k1), pack_bf16(k2, k3));
            *reinterpret_cast<uint2*>(&sm->K0[i * KPAD + j]) = pk;
        }
        if (t < NN / 2) reinterpret_cast<uint32_t*>(sm->zbp)[t] = 0x3F803F80u; // z = 1.0
    }
    __syncthreads();

    const int lane    = t & 31;
    const int wp      = t >> 5;         // 16 warps
    const int rowbase = wp << 4;        // 16 rows per warp
    const bool owner  = (lane & 3) == 0;
    const int  oidx   = rowbase + (lane >> 2);
    const int  q      = lane & 3;

    uint16_t* zb16 = sm->zbp;
    uint16_t* wb16 = sm->wbp;

    const uint32_t k0base = (uint32_t)__cvta_generic_to_shared(sm->K0);
    const uint32_t addrRow = k0base + 2u * ((rowbase + (lane & 15)) * KPAD + ((lane >> 4) << 3));
    const uint32_t zbase = (uint32_t)__cvta_generic_to_shared(sm->zbp) + q * 8;
    const uint32_t* wb32 = reinterpret_cast<const uint32_t*>(sm->wbp);

    // ---- load row-pass A fragments ONCE (K0 is iteration-invariant) ----
    uint32_t A0[16], A1[16], A2[16], A3[16];
    #pragma unroll
    for (int cc = 0; cc < 16; cc++)
        ldmx4(addrRow + cc * 32, A0[cc], A1[cc], A2[cc], A3[cc]);

    float u0 = 0.0f, u1 = 0.0f;         // owner-lane row potentials
    float w0f = 1.0f, w1f = 1.0f;
    float v_reg = 0.0f;                 // thread t<256: column t potential
    float z_reg = 1.0f, c_reg = 0.0f;

    // col-pass partial store slot: lanes 0-7 write 2 floats each
    const int  sjoff  = (lane < 4) ? 2 * lane : 8 + 2 * (lane - 4);
    float* const pst  = &sm->part[wp][0];

    // ---------------- 50 Sinkhorn iterations (eager rescale, tensor-core matvecs) --------
    #pragma unroll 1
    for (int it = 0; it < NITER; it++) {
        // ---- row pass: r = K0 z (A-frags in registers, B via LDS.64) ----
        {
            float d0 = 0.f, d1 = 0.f, d2 = 0.f, d3 = 0.f;
            float e0 = 0.f, e1 = 0.f, e2 = 0.f, e3 = 0.f;
            #pragma unroll
            for (int cc = 0; cc < 16; cc += 2) {
                u64 p0, p1;
                asm volatile("ld.shared.b64 %0, [%1];" : "=l"(p0) : "r"(zbase + cc * 32));
                asm volatile("ld.shared.b64 %0, [%1];" : "=l"(p1) : "r"(zbase + cc * 32 + 32));
                mma_bf16(d0, d1, d2, d3, A0[cc], A1[cc], A2[cc], A3[cc],
                         (uint32_t)p0, (uint32_t)(p0 >> 32));
                mma_bf16(e0, e1, e2, e3, A0[cc + 1], A1[cc + 1], A2[cc + 1], A3[cc + 1],
                         (uint32_t)p1, (uint32_t)(p1 >> 32));
            }
            float r0 = d0 + e0;      // row oidx
            float r1 = d2 + e2;      // row oidx+8
            float la0 = fminf(-PCOEF * (11.0f * u0 + __logf(DYC * r0)), LOGHUGE);
            float la1 = fminf(-PCOEF * (11.0f * u1 + __logf(DYC * r1)), LOGHUGE);
            u0 += EPSF * la0;
            u1 += EPSF * la1;
            w0f = __expf(10.0f * u0);
            w1f = __expf(10.0f * u1);
            if (owner) {
                wb16[oidx]     = to_bf16u(w0f);   // plain order
                wb16[oidx + 8] = to_bf16u(w1f);
            }
        }
        __syncthreads();

        // ---- col pass: partial c_j over this warp's 16 rows, via movmatrix'd frags ----
        {
            // A operand: w for rows rowbase..rowbase+15 (same for every chunk)
            uint32_t aw0 = wb32[(rowbase >> 1) + q];
            uint32_t aw1 = wb32[(rowbase >> 1) + 4 + q];
            #pragma unroll
            for (int cc = 0; cc < 16; cc++) {
                float d0 = 0.f, d1 = 0.f, d2 = 0.f, d3 = 0.f;
                float e0 = 0.f, e1 = 0.f, e2 = 0.f, e3 = 0.f;
                // j = 16cc+0..7 : B = transpose of (T00,T10)
                mma_bf16(d0, d1, d2, d3, aw0, aw0, aw1, aw1, movm(A0[cc]), movm(A1[cc]));
                // j = 16cc+8..15: B = transpose of (T01,T11)
                mma_bf16(e0, e1, e2, e3, aw0, aw0, aw1, aw1, movm(A2[cc]), movm(A3[cc]));
                if (lane < 8) {
                    float2 val = (lane < 4) ? make_float2(d0, d1) : make_float2(e0, e1);
                    *reinterpret_cast<float2*>(pst + cc * 16 + sjoff) = val;
                }
            }
        }
        __syncthreads();

        // ---- reduction + v/z update (thread t<256 owns column t) ----
        if (t < NN) {
            float c = 0.0f;
            #pragma unroll
            for (int s = 0; s < 16; s++) c += sm->part[s][t];
            c_reg = c;
            float lb = fminf(-PCOEF * (11.0f * v_reg + __logf(DXC * c)), LOGHUGE);
            v_reg += EPSF * lb;
            z_reg = __expf(10.0f * v_reg);
            zb16[pidx(t)] = to_bf16u(z_reg);
        }
        __syncthreads();
    }

    // publish final f32 state for the epilogue
    if (owner) {
        sm->w[oidx]     = w0f;
        sm->w[oidx + 8] = w1f;
    }
    if (t < NN) {
        sm->z[t]     = z_reg;
        sm->csave[t] = c_reg;
    }
    __syncthreads();

    // ---------------- Epilogue: marginals + transport --------------------------------
    const int row = t & (NN - 1);
    const int h   = t >> 8;
    {
        const uint16_t* __restrict__ kr = sm->K0 + row * KPAD + h * 128;
        const float*    __restrict__ zh = sm->z + h * 128;
        const float*    __restrict__ dr = Db + row * NN + h * 128;
        float racc = 0.f, tacc = 0.f;
        #pragma unroll 4
        for (int c = 0; c < 16; c++) {
            uint4  k4 = *reinterpret_cast<const uint4*>(kr + c * 8);
            float4 z0 = *reinterpret_cast<const float4*>(zh + c * 8);
            float4 z1 = *reinterpret_cast<const float4*>(zh + c * 8 + 4);
            float4 d0 = *reinterpret_cast<const float4*>(dr + c * 8);
            float4 d1 = *reinterpret_cast<const float4*>(dr + c * 8 + 4);

            float kz, cc, Cv;
            kz = __uint_as_float(k4.x << 16)          * z0.x; racc += kz;
            cc = __cosf(fminf(d0.x * 2.0f, PI2F)) + 1e-5f; Cv = -2.0f * __logf(cc); tacc = fmaf(kz, Cv, tacc);
            kz = __uint_as_float(k4.x & 0xFFFF0000u)  * z0.y; racc += kz;
            cc = __cosf(fminf(d0.y * 2.0f, PI2F)) + 1e-5f; Cv = -2.0f * __logf(cc); tacc = fmaf(kz, Cv, tacc);
            kz = __uint_as_float(k4.y << 16)          * z0.z; racc += kz;
            cc = __cosf(fminf(d0.z * 2.0f, PI2F)) + 1e-5f; Cv = -2.0f * __logf(cc); tacc = fmaf(kz, Cv, tacc);
            kz = __uint_as_float(k4.y & 0xFFFF0000u)  * z0.w; racc += kz;
            cc = __cosf(fminf(d0.w * 2.0f, PI2F)) + 1e-5f; Cv = -2.0f * __logf(cc); tacc = fmaf(kz, Cv, tacc);
            kz = __uint_as_float(k4.z << 16)          * z1.x; racc += kz;
            cc = __cosf(fminf(d1.x * 2.0f, PI2F)) + 1e-5f; Cv = -2.0f * __logf(cc); tacc = fmaf(kz, Cv, tacc);
            kz = __uint_as_float(k4.z & 0xFFFF0000u)  * z1.y; racc += kz;
            cc = __cosf(fminf(d1.y * 2.0f, PI2F)) + 1e-5f; Cv = -2.0f * __logf(cc); tacc = fmaf(kz, Cv, tacc);
            kz = __uint_as_float(k4.w << 16)          * z1.z; racc += kz;
            cc = __cosf(fminf(d1.z * 2.0f, PI2F)) + 1e-5f; Cv = -2.0f * __logf(cc); tacc = fmaf(kz, Cv, tacc);
            kz = __uint_as_float(k4.w & 0xFFFF0000u)  * z1.w; racc += kz;
            cc = __cosf(fminf(d1.w * 2.0f, PI2F)) + 1e-5f; Cv = -2.0f * __logf(cc); tacc = fmaf(kz, Cv, tacc);
        }
        sm->part[h][row]     = racc;
        sm->part[2 + h][row] = tacc;
    }
    __syncthreads();

    float val = 0.0f;
    if (t < NN) {
        float w_  = sm->w[t];
        float rm  = DYC * w_ * (sm->part[0][t] + sm->part[1][t]);
        float klr = rm * __logf(rm + 1e-10f) - rm + 1.0f;
        float tp  = w_ * (sm->part[2][t] + sm->part[3][t]) * (DXC * DYC);
        float cm  = DXC * sm->z[t] * sm->csave[t];
        float klc = cm * __logf(cm + 1e-10f) - cm + 1.0f;
        val = klr * DXC + klc * DYC + tp;
    }
    #pragma unroll
    for (int o = 16; o; o >>= 1) val += __shfl_down_sync(0xFFFFFFFFu, val, o);
    if (t < NN && lane == 0) sm->red[wp] = val;
    __syncthreads();
    if (t == 0) {
        float s = 0.0f;
        #pragma unroll
        for (int i = 0; i < 8; i++) s += sm->red[i];
        out[b] = s;
    }
}

extern "C" void kernel_launch(void* const* d_in, const int* in_sizes, int n_in,
                              void* d_out, int out_size)
{
    const float* D = (const float*)d_in[0];
    float* out = (float*)d_out;
    (void)in_sizes; (void)n_in; (void)out_size;
    size_t smem = sizeof(Smem);
    cudaFuncSetAttribute(wfr_kernel, cudaFuncAttributeMaxDynamicSharedMemorySize, (int)smem);
    wfr_kernel<<<NB, 512, smem>>>(D, out);
}

// round 8
// speedup vs baseline: 1.2019x; 1.2019x over previous
#include <cuda_runtime.h>
#include <cuda_bf16.h>
#include <cstdint>

#define NITER   50
#define EPSF    0.1f
#define PCOEF   (1.0f/1.1f)
#define LOGHUGE 69.07755279f   /* log(1e30) */
#define NB      256
#define NN      256
#define NLOC    128            /* rows per CTA (cluster of 2) */
#define KPAD    264            /* padded row length (bf16): 528B stride */
#define DXC     (1.0f/256.0f)
#define DYC     (1.0f/256.0f)
#define PI2F    1.57079632679489662f

typedef unsigned long long u64;

struct __align__(16) Smem {
    uint16_t K0[NLOC * KPAD];  // 67584 B: local half of K0 (rows rank*128..+128)
    uint16_t zbp[NN];          // packed bf16 z (global cols), B-frag order
    uint16_t wbp[NLOC];        // packed bf16 w (local rows), B-frag order
    float cpl[NN];             // this CTA's col partials
    float cpr[2][NN];          // peer-written col partials (parity buffers)
    float z[NN];               // f32 z (epilogue)
    float w[NLOC];             // f32 w local (epilogue)
    float csave[NN];           // final summed col sums
    float part[4][NLOC];       // epilogue scratch
    float red[8];
    float lossx;               // peer loss partial (rank0 only)
};

__device__ __forceinline__ unsigned pack_bf16(float a, float b) {
    __nv_bfloat162 h = __floats2bfloat162_rn(a, b);
    return *reinterpret_cast<unsigned*>(&h);
}
__device__ __forceinline__ uint16_t to_bf16u(float a) {
    __nv_bfloat16 h = __float2bfloat16(a);
    return *reinterpret_cast<uint16_t*>(&h);
}
// packed B-frag position for index j within chunks of 16
__device__ __forceinline__ int pidx(int j) {
    return (j & ~15) | (((j & 7) >> 1) << 2) | (((j >> 3) & 1) << 1) | (j & 1);
}
__device__ __forceinline__ void ldmx4(uint32_t addr, uint32_t& r0, uint32_t& r1, uint32_t& r2, uint32_t& r3) {
    asm volatile("ldmatrix.sync.aligned.m8n8.x4.shared.b16 {%0,%1,%2,%3}, [%4];"
                 : "=r"(r0), "=r"(r1), "=r"(r2), "=r"(r3) : "r"(addr));
}
__device__ __forceinline__ void ldmx4t(uint32_t addr, uint32_t& r0, uint32_t& r1, uint32_t& r2, uint32_t& r3) {
    asm volatile("ldmatrix.sync.aligned.m8n8.x4.trans.shared.b16 {%0,%1,%2,%3}, [%4];"
                 : "=r"(r0), "=r"(r1), "=r"(r2), "=r"(r3) : "r"(addr));
}
__device__ __forceinline__ void mma_bf16(float& d0, float& d1, float& d2, float& d3,
                                         uint32_t a0, uint32_t a1, uint32_t a2, uint32_t a3,
                                         uint32_t b0, uint32_t b1) {
    asm volatile("mma.sync.aligned.m16n8k16.row.col.f32.bf16.bf16.f32 "
                 "{%0,%1,%2,%3},{%4,%5,%6,%7},{%8,%9},{%0,%1,%2,%3};"
                 : "+f"(d0), "+f"(d1), "+f"(d2), "+f"(d3)
                 : "r"(a0), "r"(a1), "r"(a2), "r"(a3), "r"(b0), "r"(b1));
}
__device__ __forceinline__ uint32_t cta_rank() {
    uint32_t r; asm("mov.u32 %0, %%cluster_ctarank;" : "=r"(r)); return r;
}
__device__ __forceinline__ uint32_t mapa_u32(uint32_t laddr, uint32_t peer) {
    uint32_t r; asm("mapa.shared::cluster.u32 %0, %1, %2;" : "=r"(r) : "r"(laddr), "r"(peer));
    return r;
}
__device__ __forceinline__ void st_cluster_f32(uint32_t addr, float v) {
    asm volatile("st.shared::cluster.f32 [%0], %1;" :: "r"(addr), "f"(v) : "memory");
}
__device__ __forceinline__ void cluster_barrier() {
    asm volatile("barrier.cluster.arrive.aligned;" ::: "memory");
    asm volatile("barrier.cluster.wait.aligned;" ::: "memory");
}

__global__ void __launch_bounds__(256, 2) __cluster_dims__(2, 1, 1)
wfr_kernel(const float* __restrict__ D, float* __restrict__ out)
{
    extern __shared__ char smraw[];
    Smem* sm = reinterpret_cast<Smem*>(smraw);
    const int t = threadIdx.x;
    const uint32_t rank = cta_rank();
    const int batch = blockIdx.x >> 1;
    const float* __restrict__ Db = D + (size_t)batch * (NN * NN);
    const float* __restrict__ Dl = Db + ((size_t)rank << 15);   // this CTA's 128 rows

    // ---------------- Prologue: local half of K0 = (cos(min(2D,pi/2))+1e-5)^20 ---------
    {
        const float4* __restrict__ D4 = reinterpret_cast<const float4*>(Dl);
        #pragma unroll 4
        for (int k = 0; k < 32; k++) {
            int i4 = t + k * 256;
            float4 d = D4[i4];
            int e = i4 << 2;
            int i = e >> 8, j = e & (NN - 1);
            float c0 = __cosf(fminf(d.x * 2.0f, PI2F)) + 1e-5f;
            float c1 = __cosf(fminf(d.y * 2.0f, PI2F)) + 1e-5f;
            float c2 = __cosf(fminf(d.z * 2.0f, PI2F)) + 1e-5f;
            float c3 = __cosf(fminf(d.w * 2.0f, PI2F)) + 1e-5f;
            float k0 = exp2f(20.0f * __log2f(c0));
            float k1 = exp2f(20.0f * __log2f(c1));
            float k2 = exp2f(20.0f * __log2f(c2));
            float k3 = exp2f(20.0f * __log2f(c3));
            uint2 pk = make_uint2(pack_bf16(k0, k1), pack_bf16(k2, k3));
            *reinterpret_cast<uint2*>(&sm->K0[i * KPAD + j]) = pk;
        }
        if (t < NN / 2) reinterpret_cast<uint32_t*>(sm->zbp)[t] = 0x3F803F80u; // z = 1
    }
    __syncthreads();

    const int lane    = t & 31;
    const int wp      = t >> 5;          // 8 warps
    const int rowbase = wp << 4;         // 16 local rows per warp (row pass)
    const int colbase = wp << 5;         // 32 global cols per warp (col pass)
    const bool owner  = (lane & 3) == 0;
    const int  oidx   = rowbase + (lane >> 2);
    const int  q      = lane & 3;

    const uint32_t k0base = (uint32_t)__cvta_generic_to_shared(sm->K0);
    const uint32_t addrRow = k0base + 2u * ((rowbase + (lane & 15)) * KPAD + ((lane >> 4) << 3));
    const uint32_t addrC0  = k0base + 2u * (((lane & 7) + ((lane & 16) >> 1)) * KPAD + colbase + (lane & 8));
    const uint32_t addrC1  = addrC0 + 32u;   // +16 columns
    const uint32_t zbase = (uint32_t)__cvta_generic_to_shared(sm->zbp) + q * 8;
    const uint32_t wbase = (uint32_t)__cvta_generic_to_shared(sm->wbp) + q * 8;
    const uint32_t peerCpr = mapa_u32((uint32_t)__cvta_generic_to_shared(sm->cpr), rank ^ 1u);

    // ---- load row-pass A fragments ONCE (local rows x all 256 cols) ----
    uint32_t A0[16], A1[16], A2[16], A3[16];
    #pragma unroll
    for (int cc = 0; cc < 16; cc++)
        ldmx4(addrRow + cc * 32, A0[cc], A1[cc], A2[cc], A3[cc]);

    float u0 = 0.0f, u1 = 0.0f, w0f = 1.0f, w1f = 1.0f;
    float v_reg = 0.0f, z_reg = 1.0f, c_reg = 0.0f;

    // ---------------- 50 Sinkhorn iterations ----------------
    #pragma unroll 1
    for (int it = 0; it < NITER; it++) {
        // ---- row pass: r_i = sum_j K0[i][j] z_j  (frags in regs, 16 chunks) ----
        {
            float d0 = 0.f, d1 = 0.f, d2 = 0.f, d3 = 0.f;
            float e0 = 0.f, e1 = 0.f, e2 = 0.f, e3 = 0.f;
            #pragma unroll
            for (int cc = 0; cc < 16; cc += 2) {
                u64 p0, p1;
                asm volatile("ld.shared.b64 %0, [%1];" : "=l"(p0) : "r"(zbase + cc * 32));
                asm volatile("ld.shared.b64 %0, [%1];" : "=l"(p1) : "r"(zbase + cc * 32 + 32));
                mma_bf16(d0, d1, d2, d3, A0[cc], A1[cc], A2[cc], A3[cc],
                         (uint32_t)p0, (uint32_t)(p0 >> 32));
                mma_bf16(e0, e1, e2, e3, A0[cc + 1], A1[cc + 1], A2[cc + 1], A3[cc + 1],
                         (uint32_t)p1, (uint32_t)(p1 >> 32));
            }
            float r0 = d0 + e0;
            float r1 = d2 + e2;
            float la0 = fminf(-PCOEF * (11.0f * u0 + __logf(DYC * r0)), LOGHUGE);
            float la1 = fminf(-PCOEF * (11.0f * u1 + __logf(DYC * r1)), LOGHUGE);
            u0 += EPSF * la0;
            u1 += EPSF * la1;
            w0f = __expf(10.0f * u0);
            w1f = __expf(10.0f * u1);
            if (owner) {
                sm->wbp[pidx(oidx)]     = to_bf16u(w0f);
                sm->wbp[pidx(oidx + 8)] = to_bf16u(w1f);
            }
        }
        __syncthreads();

        // ---- col pass: partial c_j over local 128 rows; warp owns 32 cols ----
        const int par = it & 1;
        {
            float da0=0.f,da1=0.f,da2=0.f,da3=0.f, db0=0.f,db1=0.f,db2=0.f,db3=0.f;
            float ea0=0.f,ea1=0.f,ea2=0.f,ea3=0.f, eb0=0.f,eb1=0.f,eb2=0.f,eb3=0.f;
            #pragma unroll
            for (int cc = 0; cc < 8; cc++) {
                u64 pw;
                asm volatile("ld.shared.b64 %0, [%1];" : "=l"(pw) : "r"(wbase + cc * 32));
                uint32_t b0 = (uint32_t)pw, b1 = (uint32_t)(pw >> 32);
                uint32_t a0, a1, a2, a3;
                ldmx4t(addrC0 + cc * (16 * 2 * KPAD), a0, a1, a2, a3);
                if (cc & 1) mma_bf16(db0, db1, db2, db3, a0, a1, a2, a3, b0, b1);
                else        mma_bf16(da0, da1, da2, da3, a0, a1, a2, a3, b0, b1);
                ldmx4t(addrC1 + cc * (16 * 2 * KPAD), a0, a1, a2, a3);
                if (cc & 1) mma_bf16(eb0, eb1, eb2, eb3, a0, a1, a2, a3, b0, b1);
                else        mma_bf16(ea0, ea1, ea2, ea3, a0, a1, a2, a3, b0, b1);
            }
            if (owner) {
                int c0i = colbase + (lane >> 2);
                float c00 = da0 + db0;   // col c0i
                float c01 = da2 + db2;   // col c0i+8
                float c10 = ea0 + eb0;   // col c0i+16
                float c11 = ea2 + eb2;   // col c0i+24
                sm->cpl[c0i]      = c00;
                sm->cpl[c0i + 8]  = c01;
                sm->cpl[c0i + 16] = c10;
                sm->cpl[c0i + 24] = c11;
                uint32_t pbase = peerCpr + (uint32_t)(par * NN + c0i) * 4u;
                st_cluster_f32(pbase,       c00);
                st_cluster_f32(pbase + 32,  c01);
                st_cluster_f32(pbase + 64,  c10);
                st_cluster_f32(pbase + 96,  c11);
            }
        }
        cluster_barrier();

        // ---- combine partials + v/z update (thread t owns global col t) ----
        {
            float c = sm->cpl[t] + sm->cpr[par][t];
            c_reg = c;
            float lb = fminf(-PCOEF * (11.0f * v_reg + __logf(DXC * c)), LOGHUGE);
            v_reg += EPSF * lb;
            z_reg = __expf(10.0f * v_reg);
            sm->zbp[pidx(t)] = to_bf16u(z_reg);
        }
        __syncthreads();
    }

    // publish final f32 state
    if (owner) {
        sm->w[oidx]     = w0f;
        sm->w[oidx + 8] = w1f;
    }
    sm->z[t]     = z_reg;
    sm->csave[t] = c_reg;
    __syncthreads();

    // ---------------- Epilogue: marginals + transport (local rows) -----------------
    const int lrow = t & (NLOC - 1);
    const int h    = t >> 7;
    {
        const uint16_t* __restrict__ kr = sm->K0 + lrow * KPAD + h * 128;
        const float*    __restrict__ zh = sm->z + h * 128;
        const float*    __restrict__ dr = Dl + lrow * NN + h * 128;
        float racc = 0.f, tacc = 0.f;
        #pragma unroll 4
        for (int c = 0; c < 16; c++) {
            uint4  k4 = *reinterpret_cast<const uint4*>(kr + c * 8);
            float4 z0 = *reinterpret_cast<const float4*>(zh + c * 8);
            float4 z1 = *reinterpret_cast<const float4*>(zh + c * 8 + 4);
            float4 d0 = *reinterpret_cast<const float4*>(dr + c * 8);
            float4 d1 = *reinterpret_cast<const float4*>(dr + c * 8 + 4);

            float kz, cc, Cv;
            kz = __uint_as_float(k4.x << 16)          * z0.x; racc += kz;
            cc = __cosf(fminf(d0.x * 2.0f, PI2F)) + 1e-5f; Cv = -2.0f * __logf(cc); tacc = fmaf(kz, Cv, tacc);
            kz = __uint_as_float(k4.x & 0xFFFF0000u)  * z0.y; racc += kz;
            cc = __cosf(fminf(d0.y * 2.0f, PI2F)) + 1e-5f; Cv = -2.0f * __logf(cc); tacc = fmaf(kz, Cv, tacc);
            kz = __uint_as_float(k4.y << 16)          * z0.z; racc += kz;
            cc = __cosf(fminf(d0.z * 2.0f, PI2F)) + 1e-5f; Cv = -2.0f * __logf(cc); tacc = fmaf(kz, Cv, tacc);
            kz = __uint_as_float(k4.y & 0xFFFF0000u)  * z0.w; racc += kz;
            cc = __cosf(fminf(d0.w * 2.0f, PI2F)) + 1e-5f; Cv = -2.0f * __logf(cc); tacc = fmaf(kz, Cv, tacc);
            kz = __uint_as_float(k4.z << 16)          * z1.x; racc += kz;
            cc = __cosf(fminf(d1.x * 2.0f, PI2F)) + 1e-5f; Cv = -2.0f * __logf(cc); tacc = fmaf(kz, Cv, tacc);
            kz = __uint_as_float(k4.z & 0xFFFF0000u)  * z1.y; racc += kz;
            cc = __cosf(fminf(d1.y * 2.0f, PI2F)) + 1e-5f; Cv = -2.0f * __logf(cc); tacc = fmaf(kz, Cv, tacc);
            kz = __uint_as_float(k4.w << 16)          * z1.z; racc += kz;
            cc = __cosf(fminf(d1.z * 2.0f, PI2F)) + 1e-5f; Cv = -2.0f * __logf(cc); tacc = fmaf(kz, Cv, tacc);
            kz = __uint_as_float(k4.w & 0xFFFF0000u)  * z1.w; racc += kz;
            cc = __cosf(fminf(d1.w * 2.0f, PI2F)) + 1e-5f; Cv = -2.0f * __logf(cc); tacc = fmaf(kz, Cv, tacc);
        }
        sm->part[h][lrow]     = racc;
        sm->part[2 + h][lrow] = tacc;
    }
    __syncthreads();

    float val = 0.0f;
    if (t < NLOC) {   // row terms for local row t
        float w_  = sm->w[t];
        float rm  = DYC * w_ * (sm->part[0][t] + sm->part[1][t]);
        float klr = rm * __logf(rm + 1e-10f) - rm + 1.0f;
        float tp  = w_ * (sm->part[2][t] + sm->part[3][t]) * (DXC * DYC);
        val = klr * DXC + tp;
    }
    if (rank == 0) {  // col terms, computed once (global cols)
        float cm  = DXC * sm->z[t] * sm->csave[t];
        float klc = cm * __logf(cm + 1e-10f) - cm + 1.0f;
        val += klc * DYC;
    }
    #pragma unroll
    for (int o = 16; o; o >>= 1) val += __shfl_down_sync(0xFFFFFFFFu, val, o);
    if (lane == 0) sm->red[wp] = val;
    __syncthreads();
    float tot = 0.0f;
    if (t == 0) {
        #pragma unroll
        for (int i = 0; i < 8; i++) tot += sm->red[i];
        if (rank == 1) {
            uint32_t dst = mapa_u32((uint32_t)__cvta_generic_to_shared(&sm->lossx), 0u);
            st_cluster_f32(dst, tot);
        }
    }
    cluster_barrier();
    if (rank == 0 && t == 0)
        out[batch] = tot + sm->lossx;
}

extern "C" void kernel_launch(void* const* d_in, const int* in_sizes, int n_in,
                              void* d_out, int out_size)
{
    const float* D = (const float*)d_in[0];
    float* out = (float*)d_out;
    (void)in_sizes; (void)n_in; (void)out_size;
    size_t smem = sizeof(Smem);
    cudaFuncSetAttribute(wfr_kernel, cudaFuncAttributeMaxDynamicSharedMemorySize, (int)smem);
    wfr_kernel<<<NB * 2, 256, smem>>>(D, out);
}